// round 12
// baseline (speedup 1.0000x reference)
#include <cuda_runtime.h>
#include <cuda_bf16.h>

typedef unsigned long long u64;

// ---- packed f32x2 helpers (sm_103a; ptxas never auto-fuses these) ----
__device__ __forceinline__ u64 pk2(float lo, float hi) {
    u64 r; asm("mov.b64 %0, {%1, %2};" : "=l"(r) : "f"(lo), "f"(hi)); return r;
}
__device__ __forceinline__ void upk2(u64 x, float& lo, float& hi) {
    asm("mov.b64 {%0, %1}, %2;" : "=f"(lo), "=f"(hi) : "l"(x));
}
__device__ __forceinline__ u64 f2fma(u64 a, u64 b, u64 c) {
    u64 d; asm("fma.rn.f32x2 %0, %1, %2, %3;" : "=l"(d) : "l"(a), "l"(b), "l"(c)); return d;
}
__device__ __forceinline__ u64 f2add(u64 a, u64 b) {
    u64 d; asm("add.rn.f32x2 %0, %1, %2;" : "=l"(d) : "l"(a), "l"(b)); return d;
}
__device__ __forceinline__ u64 f2mul(u64 a, u64 b) {
    u64 d; asm("mul.rn.f32x2 %0, %1, %2;" : "=l"(d) : "l"(a), "l"(b)); return d;
}

constexpr int B_SIZE   = 65536;
constexpr int T_STEPS  = 512;
constexpr int CHUNKS   = 16;     // time chunks of 32 rows (last: 31)
constexpr int CH_STEPS = 32;
constexpr int THREADS  = 128;    // 4 warps/block
constexpr int WARPS    = THREADS / 32;
constexpr int P_WARP   = 64;     // particles per warp (2/thread)
constexpr size_t ROWF  = (size_t)B_SIZE * 3;   // floats per time row

// RK4 on linear Bloch system y' = A y + b is an affine map per step:
//   y <- P y + c,  P = sum_{j<=4} (dtA)^j/j!,  c = (I + dtA/2 + (dtA)^2/6 + (dtA)^3/24) b dt
// A = diag(-g) (+) [[-g,-Om],[Om,-2g]],  b = (0,0,-2g). Coefs in DOUBLE once.
struct Coef { double pu, m00, m01, m10, m11, cv, cw; };

__device__ __forceinline__ Coef make_coef(float Omf, float gf, double dt) {
    double g = (double)gf, Om = (double)Omf;
    double b00 = -g * dt, b01 = -Om * dt, b10 = Om * dt, b11 = -2.0 * g * dt;

    double n00 = 1.0 + b00 * 0.25, n01 = b01 * 0.25;
    double n10 = b10 * 0.25,       n11 = 1.0 + b11 * 0.25;
    double t00 = b00 * n00 + b01 * n10, t01 = b00 * n01 + b01 * n11;
    double t10 = b10 * n00 + b11 * n10, t11 = b10 * n01 + b11 * n11;
    const double TH = 1.0 / 3.0;
    n00 = 1.0 + t00 * TH; n01 = t01 * TH;
    n10 = t10 * TH;       n11 = 1.0 + t11 * TH;
    t00 = b00 * n00 + b01 * n10; t01 = b00 * n01 + b01 * n11;
    t10 = b10 * n00 + b11 * n10; t11 = b10 * n01 + b11 * n11;
    double q00 = 1.0 + t00 * 0.5, q01 = t01 * 0.5;
    double q10 = t10 * 0.5,       q11 = 1.0 + t11 * 0.5;

    Coef c;
    c.m00 = 1.0 + b00 * q00 + b01 * q10;
    c.m01 =       b00 * q01 + b01 * q11;
    c.m10 =       b10 * q00 + b11 * q10;
    c.m11 = 1.0 + b10 * q01 + b11 * q11;
    c.cv = b11 * q01;
    c.cw = b11 * q11;
    double a = b00;
    c.pu = 1.0 + a * (1.0 + 0.5 * a * (1.0 + a * TH * (1.0 + 0.25 * a)));
    return c;
}

__global__ __launch_bounds__(THREADS) void bloch_rk4_kernel(
    const float* __restrict__ y0,
    const float* __restrict__ t_span,
    const float* __restrict__ params,
    float* __restrict__ out)
{
    // per warp: 2 rows (96 float4 = 1536B), double-buffered
    __shared__ float4 s_stage[2][WARPS][96];

    const int lane   = threadIdx.x & 31;
    const int warpId = threadIdx.x >> 5;
    const int gwarp  = blockIdx.x * WARPS + warpId;       // 0..16383
    const int chunk  = gwarp >> 10;                       // 0..15 (time chunk)
    const int pwarp  = gwarp & 1023;                      // particle warp 0..1023
    const int base   = pwarp * P_WARP + lane * 2;         // this thread's 2 particles

    const double dt = ((double)t_span[T_STEPS - 1] - (double)t_span[0])
                      / (double)(T_STEPS - 1);

    const float2* y02 = (const float2*)(y0 + (size_t)base * 3);
    float2 a0 = y02[0], a1 = y02[1], a2 = y02[2];
    const float2* pp  = (const float2*)(params + (size_t)base * 3);
    float2 p0 = pp[0], p1 = pp[1], p2 = pp[2];
    // particle0: u=a0.x v=a0.y w=a1.x  Om=p0.x g=p1.x
    // particle1: u=a1.y v=a2.x w=a2.y  Om=p1.y g=p2.y

    Coef c0 = make_coef(p0.x, p1.x, dt);
    Coef c1 = make_coef(p1.y, p2.y, dt);

    const u64 PU  = pk2((float)c0.pu,  (float)c1.pu);
    const u64 M00 = pk2((float)c0.m00, (float)c1.m00);
    const u64 M01 = pk2((float)c0.m01, (float)c1.m01);
    const u64 M10 = pk2((float)c0.m10, (float)c1.m10);
    const u64 M11 = pk2((float)c0.m11, (float)c1.m11);
    const u64 CV  = pk2((float)c0.cv,  (float)c1.cv);
    const u64 CW  = pk2((float)c0.cw,  (float)c1.cw);

    // ---- M32 = M^32 via 5 squarings of the affine map ----
    u64 qu = PU, q00 = M00, q01 = M01, q10 = M10, q11 = M11, qcv = CV, qcw = CW;
    #pragma unroll
    for (int s = 0; s < 5; s++) {
        u64 cross = f2mul(q01, q10);
        u64 tr    = f2add(q00, q11);
        u64 n00 = f2fma(q00, q00, cross);
        u64 n11 = f2fma(q11, q11, cross);
        u64 n01 = f2mul(q01, tr);
        u64 n10 = f2mul(q10, tr);
        u64 ncv = f2fma(q00, qcv, f2fma(q01, qcw, qcv));
        u64 ncw = f2fma(q10, qcv, f2fma(q11, qcw, qcw));
        qu  = f2mul(qu, qu);
        q00 = n00; q01 = n01; q10 = n10; q11 = n11; qcv = ncv; qcw = ncw;
    }

    // state at chunk start: apply M32 `chunk` times
    u64 u = pk2(a0.x, a1.y);
    u64 v = pk2(a0.y, a2.x);
    u64 w = pk2(a1.x, a2.y);
    for (int j = 0; j < chunk; j++) {
        u      = f2mul(qu, u);
        u64 nv = f2fma(q00, v, f2fma(q01, w, qcv));
        u64 nw = f2fma(q10, v, f2fma(q11, w, qcw));
        v = nv; w = nw;
    }

    if (chunk == 0) {   // row 0 passthrough
        float2* o = (float2*)(out + (size_t)base * 3);
        o[0] = a0; o[1] = a1; o[2] = a2;
    }

    const int nsteps = (chunk == CHUNKS - 1) ? (CH_STEPS - 1) : CH_STEPS;  // 31 or 32
    const int npairs = nsteps >> 1;
    const bool tail  = nsteps & 1;

    // staging pointers: row0 at float2-offset 0, row1 at 96 (=48 float4)
    float2* st_r0[2] = { (float2*)&s_stage[0][warpId][0] + lane * 3,
                         (float2*)&s_stage[1][warpId][0] + lane * 3 };
    float2* st_r1[2] = { (float2*)&s_stage[0][warpId][0] + 96 + lane * 3,
                         (float2*)&s_stage[1][warpId][0] + 96 + lane * 3 };

    float* orow = out + (size_t)(chunk * CH_STEPS + 1) * ROWF
                      + (size_t)pwarp * (P_WARP * 3);

    for (int p = 0; p < npairs; p++) {
        const int b = p & 1;
        float uu0, uu1, vv0, vv1, ww0, ww1;

        // row A
        u      = f2mul(PU, u);
        u64 nv = f2fma(M00, v, f2fma(M01, w, CV));
        u64 nw = f2fma(M10, v, f2fma(M11, w, CW));
        v = nv; w = nw;
        upk2(u, uu0, uu1); upk2(v, vv0, vv1); upk2(w, ww0, ww1);
        st_r0[b][0] = make_float2(uu0, vv0);
        st_r0[b][1] = make_float2(ww0, uu1);
        st_r0[b][2] = make_float2(vv1, ww1);

        // row B
        u  = f2mul(PU, u);
        nv = f2fma(M00, v, f2fma(M01, w, CV));
        nw = f2fma(M10, v, f2fma(M11, w, CW));
        v = nv; w = nw;
        upk2(u, uu0, uu1); upk2(v, vv0, vv1); upk2(w, ww0, ww1);
        st_r1[b][0] = make_float2(uu0, vv0);
        st_r1[b][1] = make_float2(ww0, uu1);
        st_r1[b][2] = make_float2(vv1, ww1);
        __syncwarp();

        // 3 fully-occupied STG.128 covering rows A (48 f4) + B (48 f4)
        const float4* sbuf = &s_stage[b][warpId][0];
        float4* gA = (float4*)orow;
        float4* gB = (float4*)(orow + ROWF);
        // STG1: row A [0..31]
        __stcs(gA + lane, sbuf[lane]);
        // STG2: lanes 0-15 -> row A [32..47]; lanes 16-31 -> row B [0..15]
        {
            float4* dst = (lane < 16) ? (gA + 32 + lane) : (gB + (lane - 16));
            int     src = (lane < 16) ? (32 + lane)      : (48 + (lane - 16));
            __stcs(dst, sbuf[src]);
        }
        // STG3: row B [16..47]
        __stcs(gB + 16 + lane, sbuf[64 + lane]);

        orow += 2 * ROWF;
        // double buffer: WAR on this buffer is 2 syncwarps away
    }

    if (tail) {   // last chunk's odd 31st row
        float uu0, uu1, vv0, vv1, ww0, ww1;
        u      = f2mul(PU, u);
        u64 nv = f2fma(M00, v, f2fma(M01, w, CV));
        u64 nw = f2fma(M10, v, f2fma(M11, w, CW));
        v = nv; w = nw;
        upk2(u, uu0, uu1); upk2(v, vv0, vv1); upk2(w, ww0, ww1);
        const int b = npairs & 1;
        st_r0[b][0] = make_float2(uu0, vv0);
        st_r0[b][1] = make_float2(ww0, uu1);
        st_r0[b][2] = make_float2(vv1, ww1);
        __syncwarp();
        const float4* sbuf = &s_stage[b][warpId][0];
        float4* gA = (float4*)orow;
        __stcs(gA + lane, sbuf[lane]);
        if (lane < 16)
            __stcs(gA + 32 + lane, sbuf[32 + lane]);
    }
}

extern "C" void kernel_launch(void* const* d_in, const int* in_sizes, int n_in,
                              void* d_out, int out_size) {
    const float* y0     = (const float*)d_in[0];
    const float* t_span = (const float*)d_in[1];
    const float* params = (const float*)d_in[2];
    float* out          = (float*)d_out;

    // 16384 warps = 1024 particle-warps x 16 time chunks; 4 warps/block
    const int grid = (1024 * CHUNKS) / WARPS;   // 4096 blocks
    bloch_rk4_kernel<<<grid, THREADS>>>(y0, t_span, params, out);
}

// round 13
// speedup vs baseline: 1.7815x; 1.7815x over previous
#include <cuda_runtime.h>
#include <cuda_bf16.h>

typedef unsigned long long u64;

// ---- packed f32x2 helpers (sm_103a; ptxas never auto-fuses these) ----
__device__ __forceinline__ u64 pk2(float lo, float hi) {
    u64 r; asm("mov.b64 %0, {%1, %2};" : "=l"(r) : "f"(lo), "f"(hi)); return r;
}
__device__ __forceinline__ void upk2(u64 x, float& lo, float& hi) {
    asm("mov.b64 {%0, %1}, %2;" : "=f"(lo), "=f"(hi) : "l"(x));
}
__device__ __forceinline__ u64 f2fma(u64 a, u64 b, u64 c) {
    u64 d; asm("fma.rn.f32x2 %0, %1, %2, %3;" : "=l"(d) : "l"(a), "l"(b), "l"(c)); return d;
}
__device__ __forceinline__ u64 f2add(u64 a, u64 b) {
    u64 d; asm("add.rn.f32x2 %0, %1, %2;" : "=l"(d) : "l"(a), "l"(b)); return d;
}
__device__ __forceinline__ u64 f2mul(u64 a, u64 b) {
    u64 d; asm("mul.rn.f32x2 %0, %1, %2;" : "=l"(d) : "l"(a), "l"(b)); return d;
}

constexpr int B_SIZE   = 65536;
constexpr int T_STEPS  = 512;
constexpr int CHUNKS   = 4;                    // time chunks of 128 rows (last: 127)
constexpr int CH_STEPS = 128;
constexpr int THREADS  = 128;
constexpr int SLOTS    = B_SIZE * 3 / 4;       // 49152 float4 slots per row
constexpr int BLK_PER_CHUNK = SLOTS / THREADS; // 384
constexpr size_t ROWF4 = (size_t)SLOTS;        // float4s per time row

// RK4 on linear Bloch system y' = A y + b is an affine map per step:
//   y <- P y + c,  P = sum_{j<=4} (dtA)^j/j!,  c = (I + dtA/2 + (dtA)^2/6 + (dtA)^3/24) b dt
// A = diag(-g) (+) [[-g,-Om],[Om,-2g]],  b = (0,0,-2g). Coefs in DOUBLE once.
struct Coef { double pu, m00, m01, m10, m11, cv, cw; };

__device__ __forceinline__ Coef make_coef(float Omf, float gf, double dt) {
    double g = (double)gf, Om = (double)Omf;
    double b00 = -g * dt, b01 = -Om * dt, b10 = Om * dt, b11 = -2.0 * g * dt;

    double n00 = 1.0 + b00 * 0.25, n01 = b01 * 0.25;
    double n10 = b10 * 0.25,       n11 = 1.0 + b11 * 0.25;
    double t00 = b00 * n00 + b01 * n10, t01 = b00 * n01 + b01 * n11;
    double t10 = b10 * n00 + b11 * n10, t11 = b10 * n01 + b11 * n11;
    const double TH = 1.0 / 3.0;
    n00 = 1.0 + t00 * TH; n01 = t01 * TH;
    n10 = t10 * TH;       n11 = 1.0 + t11 * TH;
    t00 = b00 * n00 + b01 * n10; t01 = b00 * n01 + b01 * n11;
    t10 = b10 * n00 + b11 * n10; t11 = b10 * n01 + b11 * n11;
    double q00 = 1.0 + t00 * 0.5, q01 = t01 * 0.5;
    double q10 = t10 * 0.5,       q11 = 1.0 + t11 * 0.5;

    Coef c;
    c.m00 = 1.0 + b00 * q00 + b01 * q10;
    c.m01 =       b00 * q01 + b01 * q11;
    c.m10 =       b10 * q00 + b11 * q10;
    c.m11 = 1.0 + b10 * q01 + b11 * q11;
    c.cv = b11 * q01;
    c.cw = b11 * q11;
    double a = b00;
    c.pu = 1.0 + a * (1.0 + 0.5 * a * (1.0 + a * TH * (1.0 + 0.25 * a)));
    return c;
}

// Thread k owns output float4 slot k of every row (floats 4k..4k+3).
// k = 3m + r  ->  slot covers a 4-float window (offset r) of the 6-float span
// of particles p0 = 4m+r and p0+1. Thread integrates that pair (redundantly
// with neighbors for shared particles — deterministic, identical results)
// and emits ONE coalesced STG.128 per row. No SMEM, no syncs.
__global__ __launch_bounds__(THREADS) void bloch_rk4_kernel(
    const float* __restrict__ y0,
    const float* __restrict__ t_span,
    const float* __restrict__ params,
    float* __restrict__ out)
{
    const int chunk  = blockIdx.x / BLK_PER_CHUNK;            // 0..3
    const int kblock = blockIdx.x - chunk * BLK_PER_CHUNK;
    const int k      = kblock * THREADS + threadIdx.x;        // slot 0..49151

    const int m  = k / 3;
    const int r  = k - 3 * m;           // 0,1,2
    const int p0 = 4 * m + r;           // first particle of this thread's pair

    const bool isA = (r == 0);
    const bool isB = (r == 1);

    const double dt = ((double)t_span[T_STEPS - 1] - (double)t_span[0])
                      / (double)(T_STEPS - 1);

    // scalar loads (p0*3 may be odd -> no vector alignment guarantees)
    const float* yp = y0 + (size_t)p0 * 3;
    float yu0 = yp[0], yv0 = yp[1], yw0 = yp[2];
    float yu1 = yp[3], yv1 = yp[4], yw1 = yp[5];
    const float* pr = params + (size_t)p0 * 3;
    float Om0 = pr[0], g0 = pr[2];
    float Om1 = pr[3], g1 = pr[5];

    Coef c0 = make_coef(Om0, g0, dt);
    Coef c1 = make_coef(Om1, g1, dt);

    const u64 PU  = pk2((float)c0.pu,  (float)c1.pu);
    const u64 M00 = pk2((float)c0.m00, (float)c1.m00);
    const u64 M01 = pk2((float)c0.m01, (float)c1.m01);
    const u64 M10 = pk2((float)c0.m10, (float)c1.m10);
    const u64 M11 = pk2((float)c0.m11, (float)c1.m11);
    const u64 CV  = pk2((float)c0.cv,  (float)c1.cv);
    const u64 CW  = pk2((float)c0.cw,  (float)c1.cw);

    // ---- M128 = M^128 via 7 squarings of the affine map ----
    u64 qu = PU, q00 = M00, q01 = M01, q10 = M10, q11 = M11, qcv = CV, qcw = CW;
    #pragma unroll
    for (int s = 0; s < 7; s++) {
        u64 cross = f2mul(q01, q10);
        u64 tr    = f2add(q00, q11);
        u64 n00 = f2fma(q00, q00, cross);
        u64 n11 = f2fma(q11, q11, cross);
        u64 n01 = f2mul(q01, tr);
        u64 n10 = f2mul(q10, tr);
        u64 ncv = f2fma(q00, qcv, f2fma(q01, qcw, qcv));
        u64 ncw = f2fma(q10, qcv, f2fma(q11, qcw, qcw));
        qu  = f2mul(qu, qu);
        q00 = n00; q01 = n01; q10 = n10; q11 = n11; qcv = ncv; qcw = ncw;
    }

    // state at chunk start: apply M128 `chunk` times (<=3)
    u64 u = pk2(yu0, yu1);
    u64 v = pk2(yv0, yv1);
    u64 w = pk2(yw0, yw1);
    for (int j = 0; j < chunk; j++) {
        u      = f2mul(qu, u);
        u64 nv = f2fma(q00, v, f2fma(q01, w, qcv));
        u64 nw = f2fma(q10, v, f2fma(q11, w, qcw));
        v = nv; w = nw;
    }

    if (chunk == 0) {   // row 0 passthrough: straight float4 copy of y0
        ((float4*)out)[k] = ((const float4*)y0)[k];
    }

    const int nsteps = (chunk == CHUNKS - 1) ? (CH_STEPS - 1) : CH_STEPS;

    float4* outp = (float4*)out + (size_t)(chunk * CH_STEPS + 1) * ROWF4 + k;

    for (int t = 0; t < nsteps; t++) {
        // one RK4 step == one affine map: 5 f32x2 ops
        u      = f2mul(PU, u);
        u64 nv = f2fma(M00, v, f2fma(M01, w, CV));
        u64 nw = f2fma(M10, v, f2fma(M11, w, CW));
        v = nv; w = nw;

        // window select (warp-uniform-per-thread predicates, SELs not branches)
        float u0, u1, v0, v1, w0, w1;
        upk2(u, u0, u1);
        upk2(v, v0, v1);
        upk2(w, w0, w1);
        float x0 = isA ? u0 : (isB ? v0 : w0);
        float x1 = isA ? v0 : (isB ? w0 : u1);
        float x2 = isA ? w0 : (isB ? u1 : v1);
        float x3 = isA ? u1 : (isB ? v1 : w1);

        __stcs(outp, make_float4(x0, x1, x2, x3));
        outp += ROWF4;
    }
}

extern "C" void kernel_launch(void* const* d_in, const int* in_sizes, int n_in,
                              void* d_out, int out_size) {
    const float* y0     = (const float*)d_in[0];
    const float* t_span = (const float*)d_in[1];
    const float* params = (const float*)d_in[2];
    float* out          = (float*)d_out;

    const int grid = BLK_PER_CHUNK * CHUNKS;   // 1536 blocks x 128 threads
    bloch_rk4_kernel<<<grid, THREADS>>>(y0, t_span, params, out);
}

// round 14
// speedup vs baseline: 2.0465x; 1.1487x over previous
#include <cuda_runtime.h>
#include <cuda_bf16.h>

typedef unsigned long long u64;

// ---- packed f32x2 helpers (sm_103a; ptxas never auto-fuses these) ----
__device__ __forceinline__ u64 pk2(float lo, float hi) {
    u64 r; asm("mov.b64 %0, {%1, %2};" : "=l"(r) : "f"(lo), "f"(hi)); return r;
}
__device__ __forceinline__ void upk2(u64 x, float& lo, float& hi) {
    asm("mov.b64 {%0, %1}, %2;" : "=f"(lo), "=f"(hi) : "l"(x));
}
__device__ __forceinline__ u64 f2fma(u64 a, u64 b, u64 c) {
    u64 d; asm("fma.rn.f32x2 %0, %1, %2, %3;" : "=l"(d) : "l"(a), "l"(b), "l"(c)); return d;
}
__device__ __forceinline__ u64 f2add(u64 a, u64 b) {
    u64 d; asm("add.rn.f32x2 %0, %1, %2;" : "=l"(d) : "l"(a), "l"(b)); return d;
}
__device__ __forceinline__ u64 f2mul(u64 a, u64 b) {
    u64 d; asm("mul.rn.f32x2 %0, %1, %2;" : "=l"(d) : "l"(a), "l"(b)); return d;
}

constexpr int B_SIZE   = 65536;
constexpr int T_STEPS  = 512;
constexpr int CHUNKS   = 8;                     // 8 time chunks of 64 rows (last: 63)
constexpr int CH_STEPS = 64;
constexpr int THREADS  = 128;
constexpr int SLOTS8   = B_SIZE * 3 / 8;        // 24576 8-float slots per row
constexpr int BLK_PER_CHUNK = SLOTS8 / THREADS; // 192
constexpr size_t ROWF  = (size_t)B_SIZE * 3;    // floats per time row

// RK4 on linear Bloch system y' = A y + b is an affine map per step:
//   y <- P y + c. Coefficients built in fp32 (error ~1e-7, x512 amplification
//   ~5e-5 rel — far under 1e-3). dt derived in double (telescoped mean).
struct CoefF { float pu, m00, m01, m10, m11, cv, cw; };

__device__ __forceinline__ CoefF make_coef(float Om, float g, float dt) {
    float b00 = -g * dt, b01 = -Om * dt, b10 = Om * dt, b11 = -2.0f * g * dt;
    const float TH = 1.0f / 3.0f;

    float n00 = fmaf(b00, 0.25f, 1.0f), n01 = b01 * 0.25f;
    float n10 = b10 * 0.25f,            n11 = fmaf(b11, 0.25f, 1.0f);
    float t00 = fmaf(b00, n00, b01 * n10), t01 = fmaf(b00, n01, b01 * n11);
    float t10 = fmaf(b10, n00, b11 * n10), t11 = fmaf(b10, n01, b11 * n11);
    n00 = fmaf(t00, TH, 1.0f); n01 = t01 * TH;
    n10 = t10 * TH;            n11 = fmaf(t11, TH, 1.0f);
    t00 = fmaf(b00, n00, b01 * n10); t01 = fmaf(b00, n01, b01 * n11);
    t10 = fmaf(b10, n00, b11 * n10); t11 = fmaf(b10, n01, b11 * n11);
    float q00 = fmaf(t00, 0.5f, 1.0f), q01 = t01 * 0.5f;
    float q10 = t10 * 0.5f,            q11 = fmaf(t11, 0.5f, 1.0f);

    CoefF c;
    c.m00 = 1.0f + fmaf(b00, q00, b01 * q10);
    c.m01 =        fmaf(b00, q01, b01 * q11);
    c.m10 =        fmaf(b10, q00, b11 * q10);
    c.m11 = 1.0f + fmaf(b10, q01, b11 * q11);
    c.cv = b11 * q01;
    c.cw = b11 * q11;
    float a = b00;
    c.pu = 1.0f + a * fmaf(0.5f * a, fmaf(a * TH, fmaf(0.25f, a, 1.0f), 1.0f), 1.0f);
    return c;
}

// Affine map over a packed particle pair (f32x2 lanes).
struct Aff {
    u64 pu, m00, m01, m10, m11, cv, cw;
    __device__ __forceinline__ void step(u64& u, u64& v, u64& w) const {
        u = f2mul(pu, u);
        u64 nv = f2fma(m00, v, f2fma(m01, w, cv));
        u64 nw = f2fma(m10, v, f2fma(m11, w, cw));
        v = nv; w = nw;
    }
    __device__ __forceinline__ void square() {
        u64 cross = f2mul(m01, m10);
        u64 tr    = f2add(m00, m11);
        u64 n00 = f2fma(m00, m00, cross);
        u64 n11 = f2fma(m11, m11, cross);
        u64 n01 = f2mul(m01, tr);
        u64 n10 = f2mul(m10, tr);
        u64 ncv = f2fma(m00, cv, f2fma(m01, cw, cv));
        u64 ncw = f2fma(m10, cv, f2fma(m11, cw, cw));
        pu = f2mul(pu, pu);
        m00 = n00; m01 = n01; m10 = n10; m11 = n11; cv = ncv; cw = ncw;
    }
};

__device__ __forceinline__ Aff mk_aff(const CoefF& a, const CoefF& b) {
    Aff A;
    A.pu  = pk2(a.pu,  b.pu);
    A.m00 = pk2(a.m00, b.m00);
    A.m01 = pk2(a.m01, b.m01);
    A.m10 = pk2(a.m10, b.m10);
    A.m11 = pk2(a.m11, b.m11);
    A.cv  = pk2(a.cv,  b.cv);
    A.cw  = pk2(a.cw,  b.cw);
    return A;
}

// Thread k owns floats [8k, 8k+8) of every row (one 32B slot, STG.E.256).
// k = 3m + r -> window start offset s = (2r) mod 3 into the 12-float span of
// particles q0..q0+3, q0 = 8m + floor(8r/3). Integrate those 4 particles as
// two packed chains (redundant with neighbor threads for shared particles —
// deterministic identical results) and emit ONE 256-bit store per row.
__global__ __launch_bounds__(THREADS) void bloch_rk4_kernel(
    const float* __restrict__ y0,
    const float* __restrict__ t_span,
    const float* __restrict__ params,
    float* __restrict__ out)
{
    const int chunk = blockIdx.y;                         // 0..7
    const int k     = blockIdx.x * THREADS + threadIdx.x; // slot 0..24575

    const int m  = k / 3;
    const int r  = k - 3 * m;                 // 0,1,2
    const int q0 = 8 * m + (8 * r) / 3;       // first particle (r=0:+0, r=1:+2, r=2:+5)
    const int q3 = min(q0 + 3, B_SIZE - 1);   // clamp (r=2,m=8191 edge; lanes unused)

    const bool p1 = (r == 2);   // window offset s == 1
    const bool p2 = (r == 1);   // window offset s == 2

    const float dtf = (float)(((double)t_span[T_STEPS - 1] - (double)t_span[0])
                              / (double)(T_STEPS - 1));

    // scalar loads for 4 particles (q0..q0+2 contiguous, q3 clamped)
    const float* yp = y0 + (size_t)q0 * 3;
    const float* pr = params + (size_t)q0 * 3;
    const float* yq = y0 + (size_t)q3 * 3;
    const float* pq = params + (size_t)q3 * 3;

    CoefF ca = make_coef(pr[0], pr[2], dtf);
    CoefF cb = make_coef(pr[3], pr[5], dtf);
    CoefF cc = make_coef(pr[6], pr[8], dtf);
    CoefF cd = make_coef(pq[0], pq[2], dtf);

    Aff A0 = mk_aff(ca, cb);     // particles q0, q0+1
    Aff A1 = mk_aff(cc, cd);     // particles q0+2, q3

    // state
    u64 u0 = pk2(yp[0], yp[3]), v0 = pk2(yp[1], yp[4]), w0 = pk2(yp[2], yp[5]);
    u64 u1 = pk2(yp[6], yq[0]), v1 = pk2(yp[7], yq[1]), w1 = pk2(yp[8], yq[2]);

    // M^64 via 6 squarings; advance state to chunk start
    {
        Aff Q0 = A0, Q1 = A1;
        #pragma unroll
        for (int s = 0; s < 6; s++) { Q0.square(); Q1.square(); }
        for (int j = 0; j < chunk; j++) {
            Q0.step(u0, v0, w0);
            Q1.step(u1, v1, w1);
        }
    }

    if (chunk == 0) {   // row 0 passthrough: two float4 loads, one v8 store
        const float4* y4 = (const float4*)y0;
        float4 lo = y4[2 * k], hi = y4[2 * k + 1];
        asm volatile("st.global.v8.f32 [%0], {%1,%2,%3,%4,%5,%6,%7,%8};"
                     :: "l"(out + (size_t)8 * k),
                        "f"(lo.x), "f"(lo.y), "f"(lo.z), "f"(lo.w),
                        "f"(hi.x), "f"(hi.y), "f"(hi.z), "f"(hi.w) : "memory");
    }

    const int nsteps = (chunk == CHUNKS - 1) ? (CH_STEPS - 1) : CH_STEPS;
    float* orow = out + (size_t)(chunk * CH_STEPS + 1) * ROWF + (size_t)8 * k;

    for (int t = 0; t < nsteps; t++) {
        A0.step(u0, v0, w0);
        A1.step(u1, v1, w1);

        // 12-float span F[0..11] = [u,v,w] x particles q0..q0+3
        float F0,F1,F2,F3,F4,F5,F6,F7,F8,F9,F10,F11;
        upk2(u0, F0, F3); upk2(v0, F1, F4); upk2(w0, F2, F5);
        upk2(u1, F6, F9); upk2(v1, F7, F10); upk2(w1, F8, F11);

        // out[i] = F[i + s], s = 0/1/2 via predicated selects (no branches)
        float x0 = p2 ? F2 : (p1 ? F1 : F0);
        float x1 = p2 ? F3 : (p1 ? F2 : F1);
        float x2 = p2 ? F4 : (p1 ? F3 : F2);
        float x3 = p2 ? F5 : (p1 ? F4 : F3);
        float x4 = p2 ? F6 : (p1 ? F5 : F4);
        float x5 = p2 ? F7 : (p1 ? F6 : F5);
        float x6 = p2 ? F8 : (p1 ? F7 : F6);
        float x7 = p2 ? F9 : (p1 ? F8 : F7);

        asm volatile("st.global.v8.f32 [%0], {%1,%2,%3,%4,%5,%6,%7,%8};"
                     :: "l"(orow),
                        "f"(x0), "f"(x1), "f"(x2), "f"(x3),
                        "f"(x4), "f"(x5), "f"(x6), "f"(x7) : "memory");
        orow += ROWF;
    }
}

extern "C" void kernel_launch(void* const* d_in, const int* in_sizes, int n_in,
                              void* d_out, int out_size) {
    const float* y0     = (const float*)d_in[0];
    const float* t_span = (const float*)d_in[1];
    const float* params = (const float*)d_in[2];
    float* out          = (float*)d_out;

    dim3 grid(BLK_PER_CHUNK, CHUNKS);   // 192 x 8 = 1536 blocks
    bloch_rk4_kernel<<<grid, THREADS>>>(y0, t_span, params, out);
}